// round 12
// baseline (speedup 1.0000x reference)
#include <cuda_runtime.h>
#include <cstdint>
#include <cstddef>

#define D_MODEL 1024
#define NHEAD   16
#define DK      64
#define BATCH   4
#define SEQ     1024
#define M_TOK   (BATCH*SEQ)    // 4096

#define QB   32     // q rows per attention block
#define CK   128    // k/v chunk columns
#define KPAD 76     // padded K-chunk row length (floats) -> conflict-free LDS.128

// scratch: qh, kh, vh, o_concat, x  (5 x 16MB)
#define NPH (BATCH*NHEAD*SEQ*DK)   // 4194304
__device__ float g_scratch[(size_t)5 * NPH];

// ---------------------------------------------------------------------------
// SGEMM (NT): C[M,N] = A[M,K] * W[N,K]^T + bias  (M=4096, N=K=1024)
// MODE 0: scatter to head layout dst[((b*16+h)*1024+s)*64+d]
// MODE 1: dst[m*1024+n] = C + bias + residual
// ---------------------------------------------------------------------------
template<int MODE>
__global__ __launch_bounds__(256) void sgemm_nt(
    const float* __restrict__ A, const float* __restrict__ W,
    const float* __restrict__ bias, const float* __restrict__ res,
    float* __restrict__ dst)
{
    const int K = D_MODEL;
    __shared__ float As[8][128];
    __shared__ float Bs[8][128];
    const int tid = threadIdx.x;
    const int m0 = blockIdx.y * 128;
    const int n0 = blockIdx.x * 128;
    const int lr = tid >> 1;           // 0..127
    const int lc = (tid & 1) << 2;     // 0 or 4
    const int ty = tid >> 4;           // 0..15
    const int tx = tid & 15;           // 0..15

    float acc[8][8];
#pragma unroll
    for (int i = 0; i < 8; i++)
#pragma unroll
        for (int j = 0; j < 8; j++) acc[i][j] = 0.f;

    const float* Ap = A + (size_t)(m0 + lr) * K + lc;
    const float* Wp = W + (size_t)(n0 + lr) * K + lc;

    for (int kt = 0; kt < K; kt += 8) {
        float4 a4 = *(const float4*)(Ap + kt);
        float4 b4 = *(const float4*)(Wp + kt);
        __syncthreads();
        As[lc+0][lr] = a4.x; As[lc+1][lr] = a4.y; As[lc+2][lr] = a4.z; As[lc+3][lr] = a4.w;
        Bs[lc+0][lr] = b4.x; Bs[lc+1][lr] = b4.y; Bs[lc+2][lr] = b4.z; Bs[lc+3][lr] = b4.w;
        __syncthreads();
#pragma unroll
        for (int kk = 0; kk < 8; kk++) {
            float4 a0 = *(const float4*)&As[kk][ty*4];
            float4 a1 = *(const float4*)&As[kk][64 + ty*4];
            float4 b0 = *(const float4*)&Bs[kk][tx*4];
            float4 b1 = *(const float4*)&Bs[kk][64 + tx*4];
            float ar[8] = {a0.x,a0.y,a0.z,a0.w,a1.x,a1.y,a1.z,a1.w};
            float br[8] = {b0.x,b0.y,b0.z,b0.w,b1.x,b1.y,b1.z,b1.w};
#pragma unroll
            for (int i = 0; i < 8; i++)
#pragma unroll
                for (int j = 0; j < 8; j++)
                    acc[i][j] = fmaf(ar[i], br[j], acc[i][j]);
        }
    }

#pragma unroll
    for (int i = 0; i < 8; i++) {
        int m = m0 + ((i < 4) ? (ty*4 + i) : (64 + ty*4 + i - 4));
#pragma unroll
        for (int j = 0; j < 8; j++) {
            int n = n0 + ((j < 4) ? (tx*4 + j) : (64 + tx*4 + j - 4));
            float v = acc[i][j] + bias[n];
            if (MODE == 0) {
                int bb = m >> 10, ss = m & 1023, hh = n >> 6, dd = n & 63;
                dst[(((size_t)(bb*NHEAD + hh) * SEQ + ss) << 6) + dd] = v;
            } else {
                size_t idx = (size_t)m * D_MODEL + n;
                dst[idx] = v + res[idx];
            }
        }
    }
}

// ---------------------------------------------------------------------------
// Fused attention: per (b,h, 32-row q block):
//   scores(32x1024) in smem -> softmax -> write attn to gmem -> O = P @ V
// No 1/sqrt(dk) scaling (faithful to reference).
// ---------------------------------------------------------------------------
__global__ __launch_bounds__(256) void attn_kernel(
    const float* __restrict__ qh, const float* __restrict__ kh,
    const float* __restrict__ vh,
    float* __restrict__ attn_out, float* __restrict__ o_out)
{
    extern __shared__ float sm[];
    float* P  = sm;                  // [32][1024]
    float* Qs = P + QB*SEQ;          // [32][64]
    float* KV = Qs + QB*DK;          // [128][76] for K (padded) / [128][64] for V

    const int tid  = threadIdx.x;
    const int bh   = blockIdx.y;         // b*16 + h
    const int qb   = blockIdx.x;         // 0..31
    const int b    = bh >> 4, h = bh & 15;
    const int warp = tid >> 5, lane = tid & 31;
    const int r0   = warp * 4;           // this warp's 4 rows

    // load Q tile (contiguous copy)
    const float* qbase = qh + (size_t)bh * SEQ * DK + (size_t)qb * QB * DK;
#pragma unroll
    for (int f = tid; f < QB*DK/4; f += 256)
        ((float4*)Qs)[f] = ((const float4*)qbase)[f];

    float accO[4][2] = {{0.f,0.f},{0.f,0.f},{0.f,0.f},{0.f,0.f}};

    // ---- scores: S[i][j] = Q[i] . K[j] ----
    for (int kc = 0; kc < SEQ/CK; kc++) {
        __syncthreads();
        const float* kbase = kh + (size_t)bh * SEQ * DK + (size_t)kc * CK * DK;
        for (int f = tid; f < CK*DK/4; f += 256) {
            int j = f >> 4, k4 = f & 15;
            float4 kv4 = ((const float4*)kbase)[f];
            *(float4*)&KV[j*KPAD + k4*4] = kv4;
        }
        __syncthreads();

        float acc[4][4];
#pragma unroll
        for (int ii = 0; ii < 4; ii++)
#pragma unroll
            for (int jj = 0; jj < 4; jj++) acc[ii][jj] = 0.f;

#pragma unroll 4
        for (int k4 = 0; k4 < DK/4; k4++) {
            float4 q0 = *(const float4*)&Qs[(r0+0)*DK + k4*4];
            float4 q1 = *(const float4*)&Qs[(r0+1)*DK + k4*4];
            float4 q2 = *(const float4*)&Qs[(r0+2)*DK + k4*4];
            float4 q3 = *(const float4*)&Qs[(r0+3)*DK + k4*4];
#pragma unroll
            for (int jj = 0; jj < 4; jj++) {
                float4 kv4 = *(const float4*)&KV[(lane + 32*jj)*KPAD + k4*4];
                acc[0][jj] += q0.x*kv4.x + q0.y*kv4.y + q0.z*kv4.z + q0.w*kv4.w;
                acc[1][jj] += q1.x*kv4.x + q1.y*kv4.y + q1.z*kv4.z + q1.w*kv4.w;
                acc[2][jj] += q2.x*kv4.x + q2.y*kv4.y + q2.z*kv4.z + q2.w*kv4.w;
                acc[3][jj] += q3.x*kv4.x + q3.y*kv4.y + q3.z*kv4.z + q3.w*kv4.w;
            }
        }
#pragma unroll
        for (int ii = 0; ii < 4; ii++)
#pragma unroll
            for (int jj = 0; jj < 4; jj++)
                P[(r0+ii)*SEQ + kc*CK + lane + 32*jj] = acc[ii][jj];
    }

    // ---- softmax on this warp's own 4 rows + write attn to gmem ----
    float* attn_base = attn_out + ((size_t)(h*BATCH + b) * SEQ + (size_t)qb*QB) * SEQ;
#pragma unroll
    for (int ii = 0; ii < 4; ii++) {
        int i = r0 + ii;
        float* row = P + (size_t)i * SEQ;
        float mx = -1e30f;
        for (int c = lane; c < SEQ; c += 32) mx = fmaxf(mx, row[c]);
#pragma unroll
        for (int o = 16; o; o >>= 1) mx = fmaxf(mx, __shfl_xor_sync(0xffffffffu, mx, o));
        float ssum = 0.f;
        for (int c = lane; c < SEQ; c += 32) {
            float e = __expf(row[c] - mx);
            row[c] = e;
            ssum += e;
        }
#pragma unroll
        for (int o = 16; o; o >>= 1) ssum += __shfl_xor_sync(0xffffffffu, ssum, o);
        float inv = 1.0f / ssum;
        float* grow = attn_base + (size_t)i * SEQ;
        for (int c = lane; c < SEQ; c += 32) {
            float p = row[c] * inv;
            row[c] = p;
            grow[c] = p;
        }
    }

    // ---- O = P @ V  (P reads are warp-broadcast: warp owns its rows) ----
    for (int kc = 0; kc < SEQ/CK; kc++) {
        __syncthreads();   // all warps past previous KV use
        const float* vbase = vh + (size_t)bh * SEQ * DK + (size_t)kc * CK * DK;
        for (int f = tid; f < CK*DK/4; f += 256)
            ((float4*)KV)[f] = ((const float4*)vbase)[f];   // Vs[kk][d], stride 64
        __syncthreads();

        const float* prow = P + (size_t)r0 * SEQ + kc*CK;
#pragma unroll 4
        for (int kk = 0; kk < CK; kk++) {
            float p0 = prow[kk];
            float p1 = prow[SEQ + kk];
            float p2 = prow[2*SEQ + kk];
            float p3 = prow[3*SEQ + kk];
            float v0 = KV[kk*DK + lane];
            float v1 = KV[kk*DK + lane + 32];
            accO[0][0] = fmaf(p0, v0, accO[0][0]); accO[0][1] = fmaf(p0, v1, accO[0][1]);
            accO[1][0] = fmaf(p1, v0, accO[1][0]); accO[1][1] = fmaf(p1, v1, accO[1][1]);
            accO[2][0] = fmaf(p2, v0, accO[2][0]); accO[2][1] = fmaf(p2, v1, accO[2][1]);
            accO[3][0] = fmaf(p3, v0, accO[3][0]); accO[3][1] = fmaf(p3, v1, accO[3][1]);
        }
    }

    // write O in concat layout [b][s][h*64+d]
#pragma unroll
    for (int ii = 0; ii < 4; ii++) {
        int s_ = qb*QB + r0 + ii;
        float* dstp = o_out + ((size_t)(b*SEQ + s_) * D_MODEL) + h*DK;
        dstp[lane]      = accO[ii][0];
        dstp[lane + 32] = accO[ii][1];
    }
}

// ---------------------------------------------------------------------------
// LayerNorm over rows of x[4096][1024]
// ---------------------------------------------------------------------------
__global__ __launch_bounds__(256) void ln_kernel(
    const float* __restrict__ x, const float* __restrict__ gamma,
    const float* __restrict__ beta, float* __restrict__ y)
{
    __shared__ float red[8];
    __shared__ float bval;
    const int r = blockIdx.x;
    const int tid = threadIdx.x, lane = tid & 31, warp = tid >> 5;
    const float* xr = x + (size_t)r * D_MODEL;

    float v[4];
    float s = 0.f;
#pragma unroll
    for (int u = 0; u < 4; u++) { v[u] = xr[tid + 256*u]; s += v[u]; }
#pragma unroll
    for (int o = 16; o; o >>= 1) s += __shfl_xor_sync(0xffffffffu, s, o);
    if (lane == 0) red[warp] = s;
    __syncthreads();
    if (tid == 0) {
        float t = 0.f;
#pragma unroll
        for (int w = 0; w < 8; w++) t += red[w];
        bval = t * (1.f / D_MODEL);
    }
    __syncthreads();
    float mean = bval;

    float sq = 0.f;
#pragma unroll
    for (int u = 0; u < 4; u++) { float d = v[u] - mean; sq += d * d; }
#pragma unroll
    for (int o = 16; o; o >>= 1) sq += __shfl_xor_sync(0xffffffffu, sq, o);
    __syncthreads();   // everyone has read mean & red before reuse
    if (lane == 0) red[warp] = sq;
    __syncthreads();
    if (tid == 0) {
        float t = 0.f;
#pragma unroll
        for (int w = 0; w < 8; w++) t += red[w];
        bval = rsqrtf(t * (1.f / D_MODEL) + 1e-5f);
    }
    __syncthreads();
    float rstd = bval;

#pragma unroll
    for (int u = 0; u < 4; u++) {
        int c = tid + 256*u;
        y[(size_t)r * D_MODEL + c] = (v[u] - mean) * rstd * gamma[c] + beta[c];
    }
}

// ---------------------------------------------------------------------------
extern "C" void kernel_launch(void* const* d_in, const int* in_sizes, int n_in,
                              void* d_out, int out_size)
{
    const float* q     = (const float*)d_in[0];
    const float* k     = (const float*)d_in[1];
    const float* v     = (const float*)d_in[2];
    const float* Wq    = (const float*)d_in[3];
    const float* bq    = (const float*)d_in[4];
    const float* Wk    = (const float*)d_in[5];
    const float* bk    = (const float*)d_in[6];
    const float* Wv    = (const float*)d_in[7];
    const float* bv    = (const float*)d_in[8];
    const float* Wfc   = (const float*)d_in[9];
    const float* bfc   = (const float*)d_in[10];
    const float* gamma = (const float*)d_in[11];
    const float* beta  = (const float*)d_in[12];

    float* out      = (float*)d_out;
    float* y_out    = out;                                   // [4,1024,1024]
    float* attn_out = out + (size_t)BATCH * SEQ * D_MODEL;   // [64,1024,1024]

    void* sp = nullptr;
    cudaGetSymbolAddress(&sp, g_scratch);
    float* qh = (float*)sp;
    float* kh = qh + NPH;
    float* vh = kh + NPH;
    float* oc = vh + NPH;
    float* xb = oc + NPH;

    const size_t attn_smem = (size_t)(QB*SEQ + QB*DK + CK*KPAD) * sizeof(float); // ~178KB
    cudaFuncSetAttribute(attn_kernel, cudaFuncAttributeMaxDynamicSharedMemorySize,
                         (int)attn_smem);

    dim3 gg(D_MODEL/128, M_TOK/128);   // (8, 32)
    sgemm_nt<0><<<gg, 256>>>(q, Wq, bq, nullptr, qh);
    sgemm_nt<0><<<gg, 256>>>(k, Wk, bk, nullptr, kh);
    sgemm_nt<0><<<gg, 256>>>(v, Wv, bv, nullptr, vh);

    attn_kernel<<<dim3(SEQ/QB, BATCH*NHEAD), 256, attn_smem>>>(qh, kh, vh, attn_out, oc);

    sgemm_nt<1><<<gg, 256>>>(oc, Wfc, bfc, q, xb);
    ln_kernel<<<M_TOK, 256>>>(xb, gamma, beta, y_out);
}

// round 14
// speedup vs baseline: 1.2721x; 1.2721x over previous
#include <cuda_runtime.h>
#include <cstdint>
#include <cstddef>

#define D_MODEL 1024
#define NHEAD   16
#define DK      64
#define BATCH   4
#define SEQ     1024
#define M_TOK   (BATCH*SEQ)    // 4096

#define QB    32     // q rows per attention block
#define CK    128    // k/v chunk columns
#define KPAD  76     // padded K-chunk row length (floats): conflict-free LDS.128, mult-of-4
#define VPAD  130    // padded Vt row length: conflict-free LDS.64 (2*lane distinct per phase)
#define PSTW  128    // P chunk row stride

// scratch: qh, kh, vt, o_concat, x  (5 x 16MB)
#define NPH (BATCH*NHEAD*SEQ*DK)   // 4194304
__device__ float g_scratch[(size_t)5 * NPH];

typedef unsigned long long ull;

// ---- packed f32x2 helpers (FFMA2: 2 fp32 MACs per instruction) ----
__device__ __forceinline__ void fma2(ull &d, ull a, ull b) {
    asm("fma.rn.f32x2 %0, %1, %2, %0;" : "+l"(d) : "l"(a), "l"(b));
}
__device__ __forceinline__ ull dup2(float x) {
    ull r; unsigned u = __float_as_uint(x);
    asm("mov.b64 %0, {%1, %1};" : "=l"(r) : "r"(u));
    return r;
}
__device__ __forceinline__ float lo2(ull v) { return __uint_as_float((unsigned)v); }
__device__ __forceinline__ float hi2(ull v) { return __uint_as_float((unsigned)(v >> 32)); }

// ---------------------------------------------------------------------------
// SGEMM (NT): C[M,N] = A[M,K] * W[N,K]^T + bias  (M=4096, N=K=1024)
// MODE 0: scatter to head layout dst[((b*16+h)*1024+s)*64+d]
// MODE 1: dst[m*1024+n] = C + bias + residual
// MODE 2: scatter to transposed head layout dst[((b*16+h)*64+d)*1024+s]  (for V)
// Inner loop uses packed f32x2 FMA (pack over the j/column dimension).
// ---------------------------------------------------------------------------
template<int MODE>
__global__ __launch_bounds__(256, 2) void sgemm_nt(
    const float* __restrict__ A, const float* __restrict__ W,
    const float* __restrict__ bias, const float* __restrict__ res,
    float* __restrict__ dst)
{
    const int K = D_MODEL;
    __shared__ __align__(16) float As[8][128];
    __shared__ __align__(16) float Bs[8][128];
    const int tid = threadIdx.x;
    const int m0 = blockIdx.y * 128;
    const int n0 = blockIdx.x * 128;
    const int lr = tid >> 1;           // 0..127
    const int lc = (tid & 1) << 2;     // 0 or 4
    const int ty = tid >> 4;           // 0..15
    const int tx = tid & 15;           // 0..15

    ull acc2[8][4];
#pragma unroll
    for (int i = 0; i < 8; i++)
#pragma unroll
        for (int j = 0; j < 4; j++) acc2[i][j] = 0ull;

    const float* Ap = A + (size_t)(m0 + lr) * K + lc;
    const float* Wp = W + (size_t)(n0 + lr) * K + lc;

    // software pipeline: prefetch next k-tile during compute
    float4 a4 = *(const float4*)(Ap);
    float4 b4 = *(const float4*)(Wp);

    for (int kt = 0; kt < K; kt += 8) {
        __syncthreads();
        As[lc+0][lr] = a4.x; As[lc+1][lr] = a4.y; As[lc+2][lr] = a4.z; As[lc+3][lr] = a4.w;
        Bs[lc+0][lr] = b4.x; Bs[lc+1][lr] = b4.y; Bs[lc+2][lr] = b4.z; Bs[lc+3][lr] = b4.w;
        __syncthreads();
        if (kt + 8 < K) {
            a4 = *(const float4*)(Ap + kt + 8);
            b4 = *(const float4*)(Wp + kt + 8);
        }
#pragma unroll
        for (int kk = 0; kk < 8; kk++) {
            float4 a0 = *(const float4*)&As[kk][ty*4];
            float4 a1 = *(const float4*)&As[kk][64 + ty*4];
            ulonglong2 bp0 = *(const ulonglong2*)&Bs[kk][tx*4];
            ulonglong2 bp1 = *(const ulonglong2*)&Bs[kk][64 + tx*4];
            float av[8] = {a0.x,a0.y,a0.z,a0.w,a1.x,a1.y,a1.z,a1.w};
#pragma unroll
            for (int i = 0; i < 8; i++) {
                ull ai = dup2(av[i]);
                fma2(acc2[i][0], ai, bp0.x);
                fma2(acc2[i][1], ai, bp0.y);
                fma2(acc2[i][2], ai, bp1.x);
                fma2(acc2[i][3], ai, bp1.y);
            }
        }
    }

#pragma unroll
    for (int i = 0; i < 8; i++) {
        int m = m0 + ((i < 4) ? (ty*4 + i) : (64 + ty*4 + i - 4));
        float cv[8] = {lo2(acc2[i][0]), hi2(acc2[i][0]), lo2(acc2[i][1]), hi2(acc2[i][1]),
                       lo2(acc2[i][2]), hi2(acc2[i][2]), lo2(acc2[i][3]), hi2(acc2[i][3])};
#pragma unroll
        for (int j = 0; j < 8; j++) {
            int n = n0 + ((j < 4) ? (tx*4 + j) : (64 + tx*4 + j - 4));
            float v = cv[j] + bias[n];
            if (MODE == 0) {
                int bb = m >> 10, ss = m & 1023, hh = n >> 6, dd = n & 63;
                dst[(((size_t)(bb*NHEAD + hh) * SEQ + ss) << 6) + dd] = v;
            } else if (MODE == 2) {
                int bb = m >> 10, ss = m & 1023, hh = n >> 6, dd = n & 63;
                dst[((size_t)(bb*NHEAD + hh) * DK + dd) * SEQ + ss] = v;
            } else {
                size_t idx = (size_t)m * D_MODEL + n;
                dst[idx] = v + res[idx];
            }
        }
    }
}

// ---------------------------------------------------------------------------
// Fused attention, high-occupancy (62KB smem -> 3 CTAs/SM):
// Phase A: S-chunks = Q.K^T (packed f32x2), raw scores -> gmem (attn region),
//          flash-style running (max,sum) per row in registers (lane-local).
// Finalize: warp shuffle-reduce row stats.
// Phase B: re-read raw S (L2-hot), p = exp(s-M)*inv, overwrite attn gmem,
//          stage p chunk in smem, PV with packed f32x2 over k (V transposed).
// No 1/sqrt(dk) scaling (faithful to reference).
// ---------------------------------------------------------------------------
__global__ __launch_bounds__(256, 3) void attn_kernel(
    const float* __restrict__ qh, const float* __restrict__ kh,
    const float* __restrict__ vt,
    float* __restrict__ attn_out, float* __restrict__ o_out)
{
    extern __shared__ __align__(16) float smf[];
    float* Qs  = smf;                  // [32][64]    8KB
    float* KV  = Qs + QB*DK;           // [128][76] K chunk / [64][130] Vt chunk  38KB
    float* Pst = KV + CK*KPAD;         // [32][128]   16KB

    const int tid  = threadIdx.x;
    const int bh   = blockIdx.y;         // b*16 + h
    const int qb   = blockIdx.x;         // 0..31
    const int b    = bh >> 4, h = bh & 15;
    const int warp = tid >> 5, lane = tid & 31;
    const int r0   = warp * 4;           // this warp's 4 rows

    // load Q tile
    const float* qbase = qh + (size_t)bh * SEQ * DK + (size_t)qb * QB * DK;
    for (int f = tid; f < QB*DK/4; f += 256)
        ((float4*)Qs)[f] = ((const float4*)qbase)[f];

    float* attn_base = attn_out + ((size_t)(h*BATCH + b) * SEQ + (size_t)qb*QB) * SEQ;

    float m_run[4], l_run[4];
#pragma unroll
    for (int i = 0; i < 4; i++) { m_run[i] = -1e30f; l_run[i] = 0.f; }

    // ---------------- Phase A: scores -> gmem + running stats ----------------
    for (int kc = 0; kc < SEQ/CK; kc++) {
        __syncthreads();
        const float* kbase = kh + (size_t)bh * SEQ * DK + (size_t)kc * CK * DK;
        for (int f = tid; f < CK*DK/4; f += 256) {
            int j = f >> 4, k4 = f & 15;
            float4 t4 = ((const float4*)kbase)[f];
            *(float4*)&KV[j*KPAD + k4*4] = t4;
        }
        __syncthreads();

        ull acc2[4][4];
#pragma unroll
        for (int i = 0; i < 4; i++)
#pragma unroll
            for (int j = 0; j < 4; j++) acc2[i][j] = 0ull;

#pragma unroll 4
        for (int k4 = 0; k4 < DK/4; k4++) {
            ulonglong2 kv0 = *(const ulonglong2*)&KV[(lane      )*KPAD + k4*4];
            ulonglong2 kv1 = *(const ulonglong2*)&KV[(lane + 32 )*KPAD + k4*4];
            ulonglong2 kv2 = *(const ulonglong2*)&KV[(lane + 64 )*KPAD + k4*4];
            ulonglong2 kv3 = *(const ulonglong2*)&KV[(lane + 96 )*KPAD + k4*4];
#pragma unroll
            for (int i = 0; i < 4; i++) {
                ulonglong2 q2 = *(const ulonglong2*)&Qs[(r0+i)*DK + k4*4];
                fma2(acc2[i][0], q2.x, kv0.x); fma2(acc2[i][0], q2.y, kv0.y);
                fma2(acc2[i][1], q2.x, kv1.x); fma2(acc2[i][1], q2.y, kv1.y);
                fma2(acc2[i][2], q2.x, kv2.x); fma2(acc2[i][2], q2.y, kv2.y);
                fma2(acc2[i][3], q2.x, kv3.x); fma2(acc2[i][3], q2.y, kv3.y);
            }
        }

#pragma unroll
        for (int i = 0; i < 4; i++) {
            float s0 = lo2(acc2[i][0]) + hi2(acc2[i][0]);
            float s1 = lo2(acc2[i][1]) + hi2(acc2[i][1]);
            float s2 = lo2(acc2[i][2]) + hi2(acc2[i][2]);
            float s3 = lo2(acc2[i][3]) + hi2(acc2[i][3]);
            float* grow = attn_base + (size_t)(r0+i) * SEQ + kc*CK + lane;
            grow[0]  = s0; grow[32] = s1; grow[64] = s2; grow[96] = s3;
            float lm = fmaxf(fmaxf(s0, s1), fmaxf(s2, s3));
            float mn = fmaxf(m_run[i], lm);
            float l  = l_run[i] * __expf(m_run[i] - mn);
            l += __expf(s0 - mn); l += __expf(s1 - mn);
            l += __expf(s2 - mn); l += __expf(s3 - mn);
            m_run[i] = mn; l_run[i] = l;
        }
    }

    // ---------------- finalize row stats (warp reduce) ----------------
    float Mrow[4], Inv[4];
#pragma unroll
    for (int i = 0; i < 4; i++) {
        float M = m_run[i];
#pragma unroll
        for (int o = 16; o; o >>= 1) M = fmaxf(M, __shfl_xor_sync(0xffffffffu, M, o));
        float la = l_run[i] * __expf(m_run[i] - M);
#pragma unroll
        for (int o = 16; o; o >>= 1) la += __shfl_xor_sync(0xffffffffu, la, o);
        Mrow[i] = M;
        Inv[i]  = 1.0f / la;
    }

    // ---------------- Phase B: normalize + PV (packed over k) ----------------
    ull accO2[4][2];
#pragma unroll
    for (int i = 0; i < 4; i++) { accO2[i][0] = 0ull; accO2[i][1] = 0ull; }

    const float* vbase0 = vt + (size_t)bh * SEQ * DK;   // layout [64][1024]

    for (int kc = 0; kc < SEQ/CK; kc++) {
        __syncthreads();
        // load transposed V chunk Vt[d][kk] with VPAD=130 (odd*130 not 16B-aligned,
        // so stage at 8-byte granularity: always aligned, still coalesced LDG.64)
        for (int f = tid; f < DK*CK/2; f += 256) {
            int d = f >> 6, c2 = f & 63;       // CK/2 = 64 pairs per row
            ull t2 = *(const ull*)&vbase0[(size_t)d*SEQ + kc*CK + c2*2];
            *(ull*)&KV[d*VPAD + c2*2] = t2;
        }
        __syncthreads();

        // p = exp(s - M) * inv ; overwrite attn gmem ; stage into Pst
#pragma unroll
        for (int i = 0; i < 4; i++) {
            float* grow = attn_base + (size_t)(r0+i) * SEQ + kc*CK + lane;
            float s0 = grow[0], s1 = grow[32], s2 = grow[64], s3 = grow[96];
            float p0 = __expf(s0 - Mrow[i]) * Inv[i];
            float p1 = __expf(s1 - Mrow[i]) * Inv[i];
            float p2 = __expf(s2 - Mrow[i]) * Inv[i];
            float p3 = __expf(s3 - Mrow[i]) * Inv[i];
            grow[0]  = p0; grow[32] = p1; grow[64] = p2; grow[96] = p3;
            float* pr = Pst + (r0+i)*PSTW + lane;
            pr[0]  = p0; pr[32] = p1; pr[64] = p2; pr[96] = p3;
        }
        __syncwarp();

        const float* prow = Pst + r0*PSTW;
#pragma unroll 4
        for (int kk2 = 0; kk2 < CK/2; kk2++) {
            int kk = kk2 * 2;
            ull p0 = *(const ull*)&prow[kk];
            ull p1 = *(const ull*)&prow[PSTW + kk];
            ull p2 = *(const ull*)&prow[2*PSTW + kk];
            ull p3 = *(const ull*)&prow[3*PSTW + kk];
            ull vlo = *(const ull*)&KV[(size_t)lane*VPAD + kk];
            ull vhi = *(const ull*)&KV[(size_t)(lane+32)*VPAD + kk];
            fma2(accO2[0][0], p0, vlo); fma2(accO2[0][1], p0, vhi);
            fma2(accO2[1][0], p1, vlo); fma2(accO2[1][1], p1, vhi);
            fma2(accO2[2][0], p2, vlo); fma2(accO2[2][1], p2, vhi);
            fma2(accO2[3][0], p3, vlo); fma2(accO2[3][1], p3, vhi);
        }
    }

    // write O in concat layout [b][s][h*64+d]
#pragma unroll
    for (int i = 0; i < 4; i++) {
        int s_ = qb*QB + r0 + i;
        float* dstp = o_out + ((size_t)(b*SEQ + s_) * D_MODEL) + h*DK;
        dstp[lane]      = lo2(accO2[i][0]) + hi2(accO2[i][0]);
        dstp[lane + 32] = lo2(accO2[i][1]) + hi2(accO2[i][1]);
    }
}

// ---------------------------------------------------------------------------
// LayerNorm over rows of x[4096][1024]
// ---------------------------------------------------------------------------
__global__ __launch_bounds__(256) void ln_kernel(
    const float* __restrict__ x, const float* __restrict__ gamma,
    const float* __restrict__ beta, float* __restrict__ y)
{
    __shared__ float red[8];
    __shared__ float bval;
    const int r = blockIdx.x;
    const int tid = threadIdx.x, lane = tid & 31, warp = tid >> 5;
    const float* xr = x + (size_t)r * D_MODEL;

    float v[4];
    float s = 0.f;
#pragma unroll
    for (int u = 0; u < 4; u++) { v[u] = xr[tid + 256*u]; s += v[u]; }
#pragma unroll
    for (int o = 16; o; o >>= 1) s += __shfl_xor_sync(0xffffffffu, s, o);
    if (lane == 0) red[warp] = s;
    __syncthreads();
    if (tid == 0) {
        float t = 0.f;
#pragma unroll
        for (int w = 0; w < 8; w++) t += red[w];
        bval = t * (1.f / D_MODEL);
    }
    __syncthreads();
    float mean = bval;

    float sq = 0.f;
#pragma unroll
    for (int u = 0; u < 4; u++) { float d = v[u] - mean; sq += d * d; }
#pragma unroll
    for (int o = 16; o; o >>= 1) sq += __shfl_xor_sync(0xffffffffu, sq, o);
    __syncthreads();
    if (lane == 0) red[warp] = sq;
    __syncthreads();
    if (tid == 0) {
        float t = 0.f;
#pragma unroll
        for (int w = 0; w < 8; w++) t += red[w];
        bval = rsqrtf(t * (1.f / D_MODEL) + 1e-5f);
    }
    __syncthreads();
    float rstd = bval;

#pragma unroll
    for (int u = 0; u < 4; u++) {
        int c = tid + 256*u;
        y[(size_t)r * D_MODEL + c] = (v[u] - mean) * rstd * gamma[c] + beta[c];
    }
}

// ---------------------------------------------------------------------------
extern "C" void kernel_launch(void* const* d_in, const int* in_sizes, int n_in,
                              void* d_out, int out_size)
{
    const float* q     = (const float*)d_in[0];
    const float* k     = (const float*)d_in[1];
    const float* v     = (const float*)d_in[2];
    const float* Wq    = (const float*)d_in[3];
    const float* bq    = (const float*)d_in[4];
    const float* Wk    = (const float*)d_in[5];
    const float* bk    = (const float*)d_in[6];
    const float* Wv    = (const float*)d_in[7];
    const float* bv    = (const float*)d_in[8];
    const float* Wfc   = (const float*)d_in[9];
    const float* bfc   = (const float*)d_in[10];
    const float* gamma = (const float*)d_in[11];
    const float* beta  = (const float*)d_in[12];

    float* out      = (float*)d_out;
    float* y_out    = out;                                   // [4,1024,1024]
    float* attn_out = out + (size_t)BATCH * SEQ * D_MODEL;   // [64,1024,1024]

    void* sp = nullptr;
    cudaGetSymbolAddress(&sp, g_scratch);
    float* qh = (float*)sp;
    float* kh = qh + NPH;
    float* vt = kh + NPH;   // V in transposed head layout [bh][64][1024]
    float* oc = vt + NPH;
    float* xb = oc + NPH;

    const size_t attn_smem = (size_t)(QB*DK + CK*KPAD + QB*PSTW) * sizeof(float); // 62KB
    cudaFuncSetAttribute(attn_kernel, cudaFuncAttributeMaxDynamicSharedMemorySize,
                         (int)attn_smem);

    dim3 gg(D_MODEL/128, M_TOK/128);   // (8, 32)
    sgemm_nt<0><<<gg, 256>>>(q, Wq, bq, nullptr, qh);
    sgemm_nt<0><<<gg, 256>>>(k, Wk, bk, nullptr, kh);
    sgemm_nt<2><<<gg, 256>>>(v, Wv, bv, nullptr, vt);

    attn_kernel<<<dim3(SEQ/QB, BATCH*NHEAD), 256, attn_smem>>>(qh, kh, vt, attn_out, oc);

    sgemm_nt<1><<<gg, 256>>>(oc, Wfc, bfc, q, xb);
    ln_kernel<<<M_TOK, 256>>>(xb, gamma, beta, y_out);
}